// round 12
// baseline (speedup 1.0000x reference)
#include <cuda_runtime.h>
#include <cuda_bf16.h>

// ---------------------------------------------------------------------------
// Fused SSIM loss, separable 11-tap Gaussian, f32x2-packed (FFMA2) math.
//   result = 1 - (mean(ssim(f,s1)) + mean(ssim(f,s2))) / 2
// WARP-AUTONOMOUS tiles: each warp owns a 54x4 output tile with a private
// smem patch; no __syncthreads between phases (only __syncwarp), so warps
// de-synchronize and memory phases of some warps overlap fma phases of
// others on the same SMSP.
// Channels paired into 4 f32x2 lanes:
//   P0=(f,a)  P1=(f^2,a^2)  P2=(b,b^2)  P3=(f*a,f*b)
// smem patch [pair][row(4)][col(64)+pad8], row stride 72 ull: phase-B
// access (7g+k)*? -> bank = 8r+7g+k mod 32, all 32 lanes distinct.
// ---------------------------------------------------------------------------

#define IMG_W 512
#define IMG_H 512
#define N_PLANES 48               // B*C = 16*3
#define OUT_TW 54
#define ROW_STRIDE 72             // ull per v-row (64 cols + 8 pad)
#define PAIR_STRIDE (4 * ROW_STRIDE)     // 288 ull
#define WARP_SMEM (4 * PAIR_STRIDE)      // 1152 ull = 9216 B
#define SMEM_ULL (8 * WARP_SMEM)         // 9216 ull
#define SMEM_BYTES (SMEM_ULL * 8)        // 73728 B
#define GRID_X 10
#define GRID_Y 16                 // 16 blocks * 8 warps * 4 rows = 512
#define N_BLOCKS (GRID_X * GRID_Y * N_PLANES)   // 7680

typedef unsigned long long ull;

__device__ __forceinline__ ull pk2(float lo, float hi) {
    ull r; asm("mov.b64 %0, {%1, %2};" : "=l"(r) : "f"(lo), "f"(hi)); return r;
}
__device__ __forceinline__ void upk2(float& lo, float& hi, ull v) {
    asm("mov.b64 {%0, %1}, %2;" : "=f"(lo), "=f"(hi) : "l"(v));
}
__device__ __forceinline__ ull fma2(ull a, ull b, ull c) {
    ull d; asm("fma.rn.f32x2 %0, %1, %2, %3;" : "=l"(d) : "l"(a), "l"(b), "l"(c));
    return d;
}
__device__ __forceinline__ ull mul2(ull a, ull b) {
    ull d; asm("mul.rn.f32x2 %0, %1, %2;" : "=l"(d) : "l"(a), "l"(b));
    return d;
}

__device__ double       g_ssim_acc = 0.0;
__device__ unsigned int g_blk_cnt  = 0;

// tap t (0..10) -> distinct-weight index (symmetry)
#define TAPIDX(t) ((t) < 6 ? (t) : 10 - (t))

extern "C" __global__ void __launch_bounds__(256, 2)
ssim_fused_kernel(const float* __restrict__ F,
                  const float* __restrict__ S1,
                  const float* __restrict__ S2,
                  float* __restrict__ out) {
    extern __shared__ ull vb[];   // 8 warp patches

    const int tid  = threadIdx.x;
    const int wid  = tid >> 5;
    const int lane = tid & 31;
    const int x0   = blockIdx.x * OUT_TW;
    const int y0w  = (blockIdx.y * 8 + wid) * 4;   // warp's 4 output rows
    const int plane = blockIdx.z;
    const float* __restrict__ Fp  = F  + (size_t)plane * (IMG_H * IMG_W);
    const float* __restrict__ S1p = S1 + (size_t)plane * (IMG_H * IMG_W);
    const float* __restrict__ S2p = S2 + (size_t)plane * (IMG_H * IMG_W);
    ull* const wbase = vb + (size_t)wid * WARP_SMEM;

    // 6 distinct Gaussian taps (sigma=1.5, normalized), packed {w,w}.
    constexpr float G6[6] = {
        0.00102838f, 0.00759874f, 0.03600077f,
        0.10936055f, 0.21300554f, 0.26601173f
    };
    ull W6[6];
    #pragma unroll
    for (int t = 0; t < 6; ++t) {
        unsigned u = __float_as_uint(G6[t]);
        W6[t] = ((ull)u << 32) | u;
    }

    // ---------------- Phase A: vertical blur, lane = 2 columns --------------
    {
        const int xg0 = x0 - 5 + lane;       // col lane
        const int xg1 = xg0 + 32;            // col lane+32
        const int rbase = y0w - 5;
        const bool interior = (blockIdx.x >= 1) & (blockIdx.x <= 8) &
                              (y0w >= 8) & (y0w <= 500);

        ull a0[4][4], a1[4][4];
        #pragma unroll
        for (int j = 0; j < 4; ++j)
            #pragma unroll
            for (int p = 0; p < 4; ++p) { a0[j][p] = 0ull; a1[j][p] = 0ull; }

        if (interior) {
            const float* pf = Fp  + (rbase * IMG_W + xg0);
            const float* pa = S1p + (rbase * IMG_W + xg0);
            const float* pb = S2p + (rbase * IMG_W + xg0);
            #pragma unroll
            for (int r = 0; r < 14; ++r) {
                const float f0 = pf[r * IMG_W],      f1 = pf[r * IMG_W + 32];
                const float s0 = pa[r * IMG_W],      s1 = pa[r * IMG_W + 32];
                const float t0 = pb[r * IMG_W],      t1 = pb[r * IMG_W + 32];
                const ull P00 = pk2(f0, s0),         P10 = pk2(f1, s1);
                const ull P01 = mul2(P00, P00),      P11 = mul2(P10, P10);
                const ull P02 = pk2(t0, t0 * t0),    P12 = pk2(t1, t1 * t1);
                const ull P03 = pk2(f0 * s0, f0 * t0);
                const ull P13 = pk2(f1 * s1, f1 * t1);
                const int jlo = (r - 10) > 0 ? (r - 10) : 0;
                const int jhi = r < 3 ? r : 3;
                #pragma unroll
                for (int j = jlo; j <= jhi; ++j) {
                    const ull w = W6[TAPIDX(r - j)];
                    a0[j][0] = fma2(P00, w, a0[j][0]);
                    a0[j][1] = fma2(P01, w, a0[j][1]);
                    a0[j][2] = fma2(P02, w, a0[j][2]);
                    a0[j][3] = fma2(P03, w, a0[j][3]);
                    a1[j][0] = fma2(P10, w, a1[j][0]);
                    a1[j][1] = fma2(P11, w, a1[j][1]);
                    a1[j][2] = fma2(P12, w, a1[j][2]);
                    a1[j][3] = fma2(P13, w, a1[j][3]);
                }
            }
        } else {
            const bool ok0 = ((unsigned)xg0 < (unsigned)IMG_W);
            const bool ok1 = ((unsigned)xg1 < (unsigned)IMG_W);
            #pragma unroll
            for (int r = 0; r < 14; ++r) {
                const int ry = rbase + r;
                const bool rok = ((unsigned)ry < (unsigned)IMG_H);
                float f0 = 0.f, s0 = 0.f, t0 = 0.f;
                float f1 = 0.f, s1 = 0.f, t1 = 0.f;
                if (rok & ok0) {
                    const int idx = ry * IMG_W + xg0;
                    f0 = Fp[idx]; s0 = S1p[idx]; t0 = S2p[idx];
                }
                if (rok & ok1) {
                    const int idx = ry * IMG_W + xg1;
                    f1 = Fp[idx]; s1 = S1p[idx]; t1 = S2p[idx];
                }
                const ull P00 = pk2(f0, s0),         P10 = pk2(f1, s1);
                const ull P01 = mul2(P00, P00),      P11 = mul2(P10, P10);
                const ull P02 = pk2(t0, t0 * t0),    P12 = pk2(t1, t1 * t1);
                const ull P03 = pk2(f0 * s0, f0 * t0);
                const ull P13 = pk2(f1 * s1, f1 * t1);
                const int jlo = (r - 10) > 0 ? (r - 10) : 0;
                const int jhi = r < 3 ? r : 3;
                #pragma unroll
                for (int j = jlo; j <= jhi; ++j) {
                    const ull w = W6[TAPIDX(r - j)];
                    a0[j][0] = fma2(P00, w, a0[j][0]);
                    a0[j][1] = fma2(P01, w, a0[j][1]);
                    a0[j][2] = fma2(P02, w, a0[j][2]);
                    a0[j][3] = fma2(P03, w, a0[j][3]);
                    a1[j][0] = fma2(P10, w, a1[j][0]);
                    a1[j][1] = fma2(P11, w, a1[j][1]);
                    a1[j][2] = fma2(P12, w, a1[j][2]);
                    a1[j][3] = fma2(P13, w, a1[j][3]);
                }
            }
        }

        // store: wbase[p*288 + j*72 + col]  (32 consecutive ull per half-warp
        // group -> conflict-free STS.64)
        #pragma unroll
        for (int p = 0; p < 4; ++p)
            #pragma unroll
            for (int j = 0; j < 4; ++j) {
                wbase[p * PAIR_STRIDE + j * ROW_STRIDE + lane]      = a0[j][p];
                wbase[p * PAIR_STRIDE + j * ROW_STRIDE + lane + 32] = a1[j][p];
            }
    }
    __syncwarp();

    // ---------------- Phase B: horizontal blur + epilogue -------------------
    float lsum = 0.0f;
    {
        const int r  = lane & 3;           // output row within warp tile
        const int g  = lane >> 2;          // 0..7 column group
        const int c0 = g * 7;              // out-col base (0..49)
        const ull* __restrict__ src = wbase + r * ROW_STRIDE + c0;

        ull hb[4][7];
        #pragma unroll
        for (int p = 0; p < 4; ++p)
            #pragma unroll
            for (int j = 0; j < 7; ++j) hb[p][j] = 0ull;

        #pragma unroll
        for (int k = 0; k < 17; ++k) {
            const int jlo = (k - 10) > 0 ? (k - 10) : 0;
            const int jhi = k < 6 ? k : 6;
            #pragma unroll
            for (int p = 0; p < 4; ++p) {
                const ull w = src[p * PAIR_STRIDE + k];
                #pragma unroll
                for (int j = jlo; j <= jhi; ++j)
                    hb[p][j] = fma2(w, W6[TAPIDX(k - j)], hb[p][j]);
            }
        }

        const int limit = (OUT_TW < IMG_W - x0) ? OUT_TW : (IMG_W - x0);
        const float C1c = 1e-4f;   // 0.01^2
        const float C2c = 9e-4f;   // 0.03^2
        #pragma unroll
        for (int j = 0; j < 7; ++j) {
            if (c0 + j < limit) {
                float mu1, mu2, Bff, Baa, mu3, Bbb, Bfa, Bfb;
                upk2(mu1, mu2, hb[0][j]);
                upk2(Bff, Baa, hb[1][j]);
                upk2(mu3, Bbb, hb[2][j]);
                upk2(Bfa, Bfb, hb[3][j]);
                const float m11 = mu1 * mu1, m22 = mu2 * mu2, m33 = mu3 * mu3;
                const float m12 = mu1 * mu2, m13 = mu1 * mu3;
                const float s11 = Bff - m11;
                const float s22 = Baa - m22;
                const float s33 = Bbb - m33;
                const float s12 = Bfa - m12;
                const float s13 = Bfb - m13;
                const float n1 = (2.0f * m12 + C1c) * (2.0f * s12 + C2c);
                const float d1 = (m11 + m22 + C1c) * (s11 + s22 + C2c);
                const float n2 = (2.0f * m13 + C1c) * (2.0f * s13 + C2c);
                const float d2 = (m11 + m33 + C1c) * (s11 + s33 + C2c);
                lsum += __fdividef(n1, d1) + __fdividef(n2, d2);
            }
        }
    }

    // ---------------- reduction + self-finalizing last block ----------------
    #pragma unroll
    for (int o = 16; o; o >>= 1)
        lsum += __shfl_down_sync(0xffffffffu, lsum, o);
    __shared__ float wsum[8];
    if (lane == 0) wsum[wid] = lsum;
    __syncthreads();
    if (tid < 8) {
        float v = wsum[tid];
        #pragma unroll
        for (int o = 4; o; o >>= 1)
            v += __shfl_down_sync(0x000000ffu, v, o);
        if (tid == 0) {
            atomicAdd(&g_ssim_acc, (double)v);
            __threadfence();
            const unsigned old = atomicAdd(&g_blk_cnt, 1u);
            if (old == (unsigned)(N_BLOCKS - 1)) {
                __threadfence();
                volatile double* va = &g_ssim_acc;
                const double total = *va;
                const double npix = (double)N_PLANES * IMG_H * IMG_W;
                out[0] = (float)(1.0 - total / (2.0 * npix));
                *va = 0.0;                       // reset for next replay
                *(volatile unsigned*)&g_blk_cnt = 0u;
                __threadfence();
            }
        }
    }
}

extern "C" void kernel_launch(void* const* d_in, const int* in_sizes, int n_in,
                              void* d_out, int out_size) {
    (void)in_sizes; (void)n_in; (void)out_size;
    const float* F  = (const float*)d_in[0];
    const float* S1 = (const float*)d_in[1];
    const float* S2 = (const float*)d_in[2];
    float* out = (float*)d_out;

    cudaFuncSetAttribute(ssim_fused_kernel,
                         cudaFuncAttributeMaxDynamicSharedMemorySize,
                         SMEM_BYTES);

    dim3 grid(GRID_X, GRID_Y, N_PLANES);   // 10 x 16 x 48 = 7680 blocks
    ssim_fused_kernel<<<grid, 256, SMEM_BYTES>>>(F, S1, S2, out);
}

// round 14
// speedup vs baseline: 1.0769x; 1.0769x over previous
#include <cuda_runtime.h>
#include <cuda_bf16.h>

// ---------------------------------------------------------------------------
// Fused SSIM loss, separable 11-tap Gaussian, f32x2-packed (FFMA2) math.
//   result = 1 - (mean(ssim(f,s1)) + mean(ssim(f,s2))) / 2
// Channels paired into 4 f32x2 lanes:
//   P0=(f,a)  P1=(f^2,a^2)  P2=(b,b^2)  P3=(f*a,f*b)
// v-buffer TRANSPOSED [pair][col][row] -> conflict-free LDS.64 in phase B.
// Strip-mined 4 tiles/block; cp.async stages tile t+1's raw input rows into
// smem while tile t's phase B (pure fma) runs -> phase A never waits on DRAM.
// Border-x blocks (bx 0,9) use the direct-LDG clamped path.
// ---------------------------------------------------------------------------

#define IMG_W 512
#define IMG_H 512
#define N_PLANES 48               // B*C = 16*3
#define OUT_TW 54
#define OUT_TH 32
#define IN_TW 64
#define COL_STRIDE 33             // ull per column (32 rows + 1 pad)
#define PAIR_STRIDE (IN_TW * COL_STRIDE)
#define VB_ULL (4 * PAIR_STRIDE + 128)            // 8576 ull = 68608 B
#define RAW_ROWS 42
#define RAW_W 68                  // 64 cols + <=3 align-off + pad
#define RAW_ARR (RAW_ROWS * RAW_W)                // 2856 floats
#define RAW_FLOATS (3 * RAW_ARR)                  // 8568
#define N_CHUNKS (3 * RAW_ROWS * 17)              // 16B segs: 2142
#define SMEM_BYTES (VB_ULL * 8 + RAW_FLOATS * 4)  // 102880 B
#define TILES_PER_BLOCK 4
#define GRID_X 10
#define GRID_Y 4
#define N_BLOCKS (GRID_X * GRID_Y * N_PLANES)     // 1920

typedef unsigned long long ull;

__device__ __forceinline__ ull pk2(float lo, float hi) {
    ull r; asm("mov.b64 %0, {%1, %2};" : "=l"(r) : "f"(lo), "f"(hi)); return r;
}
__device__ __forceinline__ void upk2(float& lo, float& hi, ull v) {
    asm("mov.b64 {%0, %1}, %2;" : "=f"(lo), "=f"(hi) : "l"(v));
}
__device__ __forceinline__ ull fma2(ull a, ull b, ull c) {
    ull d; asm("fma.rn.f32x2 %0, %1, %2, %3;" : "=l"(d) : "l"(a), "l"(b), "l"(c));
    return d;
}
__device__ __forceinline__ ull mul2(ull a, ull b) {
    ull d; asm("mul.rn.f32x2 %0, %1, %2;" : "=l"(d) : "l"(a), "l"(b));
    return d;
}
__device__ __forceinline__ unsigned smem_u32(const void* p) {
    unsigned a;
    asm("{ .reg .u64 t; cvta.to.shared.u64 t, %1; cvt.u32.u64 %0, t; }"
        : "=r"(a) : "l"(p));
    return a;
}

__device__ double       g_ssim_acc = 0.0;
__device__ unsigned int g_blk_cnt  = 0;

// tap t (0..10) -> distinct-weight index (symmetry)
#define TAPIDX(t) ((t) < 6 ? (t) : 10 - (t))

extern "C" __global__ void __launch_bounds__(256, 2)
ssim_fused_kernel(const float* __restrict__ F,
                  const float* __restrict__ S1,
                  const float* __restrict__ S2,
                  float* __restrict__ out) {
    extern __shared__ ull vb[];            // vbuf then raw staging
    float* const raw = (float*)(vb + VB_ULL);

    const int tid = threadIdx.x;
    const int x0 = blockIdx.x * OUT_TW;
    const int plane = blockIdx.z;
    const float* __restrict__ Fp  = F  + (size_t)plane * (IMG_H * IMG_W);
    const float* __restrict__ S1p = S1 + (size_t)plane * (IMG_H * IMG_W);
    const float* __restrict__ S2p = S2 + (size_t)plane * (IMG_H * IMG_W);

    constexpr float G6[6] = {
        0.00102838f, 0.00759874f, 0.03600077f,
        0.10936055f, 0.21300554f, 0.26601173f
    };
    ull W6[6];
    #pragma unroll
    for (int t = 0; t < 6; ++t) {
        unsigned u = __float_as_uint(G6[t]);
        W6[t] = ((ull)u << 32) | u;
    }

    // per-thread constants
    const int colA  = tid & 63;            // phase A column 0..63
    const int chunk = tid >> 6;            // phase A 0..3 -> v-rows [chunk*8,+8)
    const int xg = x0 - 5 + colA;
    const bool colok = ((unsigned)xg < (unsigned)IMG_W);
    const bool interior_x = (blockIdx.x >= 1) & (blockIdx.x <= 8);
    ull* const dstA = vb + (size_t)colA * COL_STRIDE + chunk * 8;

    const int astart = (x0 - 5) & ~3;      // 16B-aligned staging col base
    const int aoff   = (x0 - 5) - astart;  // 0..3
    const unsigned raw_sa = smem_u32(raw);

    // staging-chunk start coords for this thread (i = tid)
    int stg_seg, stg_row, stg_arr;
    { int t2 = tid / 17; stg_seg = tid - t2 * 17;
      stg_arr = t2 / RAW_ROWS; stg_row = t2 - stg_arr * RAW_ROWS; }

    const int rowB  = tid & 31;            // phase B lanes = rows
    const int group = tid >> 5;            // 0..7
    const int c0 = group * 7;              // out-col base (0..49)
    const size_t boff = (size_t)c0 * COL_STRIDE + rowB;
    const int limit = (OUT_TW < IMG_W - x0) ? OUT_TW : (IMG_W - x0);

    // ---- stage tile 0 (interior-x blocks only) -----------------------------
    if (interior_x) {
        const int rowg0 = blockIdx.y * TILES_PER_BLOCK * OUT_TH - 5;
        int i = tid, seg = stg_seg, row = stg_row, arr = stg_arr;
        while (i < N_CHUNKS) {
            const unsigned sa = raw_sa +
                ((unsigned)(arr * RAW_ARR + row * RAW_W + seg * 4) << 2);
            const int ry = rowg0 + row;
            if ((unsigned)ry < (unsigned)IMG_H) {
                const float* gp = ((arr == 0) ? Fp : (arr == 1) ? S1p : S2p)
                                  + (ry * IMG_W + astart + seg * 4);
                asm volatile("cp.async.cg.shared.global [%0], [%1], 16;"
                             :: "r"(sa), "l"(gp));
            } else {
                asm volatile("st.shared.v4.b32 [%0], {%1,%1,%1,%1};"
                             :: "r"(sa), "r"(0u));
            }
            i += 256; seg += 1; row += 15;
            if (seg >= 17) { seg -= 17; row += 1; }
            if (row >= RAW_ROWS) { row -= RAW_ROWS; arr += 1; }
        }
        asm volatile("cp.async.commit_group;" ::: "memory");
    }

    float lsum = 0.0f;

    for (int s = 0; s < TILES_PER_BLOCK; ++s) {
        const int y0 = (blockIdx.y * TILES_PER_BLOCK + s) * OUT_TH;

        if (interior_x)
            asm volatile("cp.async.wait_group 0;" ::: "memory");
        __syncthreads();   // raw tile s visible to all (and vbuf free)

        // ---------------- Phase A: vertical blur ----------------------------
        {
            ull acc[8][4];
            #pragma unroll
            for (int j = 0; j < 8; ++j)
                #pragma unroll
                for (int p = 0; p < 4; ++p) acc[j][p] = 0ull;

            if (interior_x) {
                // read staged rows from smem; zeros pre-staged for invalid
                const float* pf = raw + 0 * RAW_ARR + chunk * 8 * RAW_W
                                      + colA + aoff;
                const float* pa = pf + RAW_ARR;
                const float* pb = pa + RAW_ARR;
                #pragma unroll
                for (int r = 0; r < 18; ++r) {
                    const float f = pf[r * RAW_W];
                    const float a = pa[r * RAW_W];
                    const float b = pb[r * RAW_W];
                    const ull P0 = pk2(f, a);
                    const ull P1 = mul2(P0, P0);
                    const ull P2 = pk2(b, b * b);
                    const ull P3 = pk2(f * a, f * b);
                    const int jlo = (r - 10) > 0 ? (r - 10) : 0;
                    const int jhi = r < 7 ? r : 7;
                    #pragma unroll
                    for (int j = jlo; j <= jhi; ++j) {
                        const ull w = W6[TAPIDX(r - j)];
                        acc[j][0] = fma2(P0, w, acc[j][0]);
                        acc[j][1] = fma2(P1, w, acc[j][1]);
                        acc[j][2] = fma2(P2, w, acc[j][2]);
                        acc[j][3] = fma2(P3, w, acc[j][3]);
                    }
                }
            } else {
                const int rbase = y0 + chunk * 8 - 5;
                #pragma unroll
                for (int r = 0; r < 18; ++r) {
                    const int ry = rbase + r;
                    float f = 0.0f, a = 0.0f, b = 0.0f;
                    if (colok && (unsigned)ry < (unsigned)IMG_H) {
                        const int idx = ry * IMG_W + xg;
                        f = Fp[idx]; a = S1p[idx]; b = S2p[idx];
                    }
                    const ull P0 = pk2(f, a);
                    const ull P1 = mul2(P0, P0);
                    const ull P2 = pk2(b, b * b);
                    const ull P3 = pk2(f * a, f * b);
                    const int jlo = (r - 10) > 0 ? (r - 10) : 0;
                    const int jhi = r < 7 ? r : 7;
                    #pragma unroll
                    for (int j = jlo; j <= jhi; ++j) {
                        const ull w = W6[TAPIDX(r - j)];
                        acc[j][0] = fma2(P0, w, acc[j][0]);
                        acc[j][1] = fma2(P1, w, acc[j][1]);
                        acc[j][2] = fma2(P2, w, acc[j][2]);
                        acc[j][3] = fma2(P3, w, acc[j][3]);
                    }
                }
            }

            #pragma unroll
            for (int p = 0; p < 4; ++p)
                #pragma unroll
                for (int j = 0; j < 8; ++j)
                    dstA[p * PAIR_STRIDE + j] = acc[j][p];
        }
        __syncthreads();   // vbuf complete; raw fully consumed

        // ---- stage tile s+1 (overlaps with phase B's fma burst) ------------
        if (interior_x && s < TILES_PER_BLOCK - 1) {
            const int rowg0 = y0 + OUT_TH - 5;
            int i = tid, seg = stg_seg, row = stg_row, arr = stg_arr;
            while (i < N_CHUNKS) {
                const unsigned sa = raw_sa +
                    ((unsigned)(arr * RAW_ARR + row * RAW_W + seg * 4) << 2);
                const int ry = rowg0 + row;
                if ((unsigned)ry < (unsigned)IMG_H) {
                    const float* gp = ((arr == 0) ? Fp : (arr == 1) ? S1p : S2p)
                                      + (ry * IMG_W + astart + seg * 4);
                    asm volatile("cp.async.cg.shared.global [%0], [%1], 16;"
                                 :: "r"(sa), "l"(gp));
                } else {
                    asm volatile("st.shared.v4.b32 [%0], {%1,%1,%1,%1};"
                                 :: "r"(sa), "r"(0u));
                }
                i += 256; seg += 1; row += 15;
                if (seg >= 17) { seg -= 17; row += 1; }
                if (row >= RAW_ROWS) { row -= RAW_ROWS; arr += 1; }
            }
            asm volatile("cp.async.commit_group;" ::: "memory");
        }

        // ---------------- Phase B: horizontal blur + epilogue ---------------
        {
            ull hb[4][7];
            #pragma unroll
            for (int p = 0; p < 4; ++p) {
                const ull* __restrict__ src = vb + (size_t)p * PAIR_STRIDE + boff;
                #pragma unroll
                for (int j = 0; j < 7; ++j) hb[p][j] = 0ull;
                #pragma unroll
                for (int k = 0; k < 17; ++k) {
                    const ull w = src[k * COL_STRIDE];
                    const int jlo = (k - 10) > 0 ? (k - 10) : 0;
                    const int jhi = k < 6 ? k : 6;
                    #pragma unroll
                    for (int j = jlo; j <= jhi; ++j)
                        hb[p][j] = fma2(w, W6[TAPIDX(k - j)], hb[p][j]);
                }
            }

            const float C1c = 1e-4f;   // 0.01^2
            const float C2c = 9e-4f;   // 0.03^2
            #pragma unroll
            for (int j = 0; j < 7; ++j) {
                if (c0 + j < limit) {
                    float mu1, mu2, Bff, Baa, mu3, Bbb, Bfa, Bfb;
                    upk2(mu1, mu2, hb[0][j]);
                    upk2(Bff, Baa, hb[1][j]);
                    upk2(mu3, Bbb, hb[2][j]);
                    upk2(Bfa, Bfb, hb[3][j]);
                    const float m11 = mu1 * mu1, m22 = mu2 * mu2;
                    const float m33 = mu3 * mu3;
                    const float m12 = mu1 * mu2, m13 = mu1 * mu3;
                    const float s11 = Bff - m11;
                    const float s22 = Baa - m22;
                    const float s33 = Bbb - m33;
                    const float s12 = Bfa - m12;
                    const float s13 = Bfb - m13;
                    const float n1 = (2.0f * m12 + C1c) * (2.0f * s12 + C2c);
                    const float d1 = (m11 + m22 + C1c) * (s11 + s22 + C2c);
                    const float n2 = (2.0f * m13 + C1c) * (2.0f * s13 + C2c);
                    const float d2 = (m11 + m33 + C1c) * (s11 + s33 + C2c);
                    lsum += __fdividef(n1, d1) + __fdividef(n2, d2);
                }
            }
        }
        // next loop-top sync protects vbuf/raw reuse
    }

    // ---------------- reduction + self-finalizing last block ----------------
    #pragma unroll
    for (int o = 16; o; o >>= 1)
        lsum += __shfl_down_sync(0xffffffffu, lsum, o);
    __shared__ float wsum[8];
    if ((tid & 31) == 0) wsum[tid >> 5] = lsum;
    __syncthreads();
    if (tid < 8) {
        float v = wsum[tid];
        #pragma unroll
        for (int o = 4; o; o >>= 1)
            v += __shfl_down_sync(0x000000ffu, v, o);
        if (tid == 0) {
            atomicAdd(&g_ssim_acc, (double)v);
            __threadfence();
            const unsigned old = atomicAdd(&g_blk_cnt, 1u);
            if (old == (unsigned)(N_BLOCKS - 1)) {
                __threadfence();
                volatile double* va = &g_ssim_acc;
                const double total = *va;
                const double npix = (double)N_PLANES * IMG_H * IMG_W;
                out[0] = (float)(1.0 - total / (2.0 * npix));
                *va = 0.0;                       // reset for next replay
                *(volatile unsigned*)&g_blk_cnt = 0u;
                __threadfence();
            }
        }
    }
}

extern "C" void kernel_launch(void* const* d_in, const int* in_sizes, int n_in,
                              void* d_out, int out_size) {
    (void)in_sizes; (void)n_in; (void)out_size;
    const float* F  = (const float*)d_in[0];
    const float* S1 = (const float*)d_in[1];
    const float* S2 = (const float*)d_in[2];
    float* out = (float*)d_out;

    cudaFuncSetAttribute(ssim_fused_kernel,
                         cudaFuncAttributeMaxDynamicSharedMemorySize,
                         SMEM_BYTES);

    dim3 grid(GRID_X, GRID_Y, N_PLANES);   // 10 x 4 x 48 = 1920 blocks
    ssim_fused_kernel<<<grid, 256, SMEM_BYTES>>>(F, S1, S2, out);
}

// round 15
// speedup vs baseline: 1.0952x; 1.0170x over previous
#include <cuda_runtime.h>
#include <cuda_bf16.h>

// ---------------------------------------------------------------------------
// Fused SSIM loss, separable 11-tap Gaussian, f32x2-packed (FFMA2) math.
//   result = 1 - (mean(ssim(f,s1)) + mean(ssim(f,s2))) / 2
// Channel pairs (phase A splits into two low-register passes):
//   Q0=(f,a)   Q1=(f*a,a^2)   [pass 1: loads f,a]
//   Q2=(f^2,b) Q3=(b^2,f*b)   [pass 2: loads f,b]
// v-buffer TRANSPOSED [pair][col][row] -> phase-B warp lanes (rows) read
// consecutive ull -> conflict-free LDS.64. Interior blocks skip border
// predicates. Two-pass phases cut regs so 3 blocks/SM (24 warps) fit.
// ---------------------------------------------------------------------------

#define IMG_W 512
#define IMG_H 512
#define N_PLANES 48               // B*C = 16*3
#define OUT_TW 54
#define OUT_TH 32
#define IN_TW 64
#define COL_STRIDE 33             // ull per column (32 rows + 1 pad)
#define PAIR_STRIDE (IN_TW * COL_STRIDE)
#define SMEM_ULL (4 * PAIR_STRIDE + 128)          // +128 overread slack
#define SMEM_BYTES (SMEM_ULL * 8)                 // 68608
#define GRID_X 10
#define GRID_Y 16
#define N_BLOCKS (GRID_X * GRID_Y * N_PLANES)     // 7680

typedef unsigned long long ull;

__device__ __forceinline__ ull pk2(float lo, float hi) {
    ull r; asm("mov.b64 %0, {%1, %2};" : "=l"(r) : "f"(lo), "f"(hi)); return r;
}
__device__ __forceinline__ void upk2(float& lo, float& hi, ull v) {
    asm("mov.b64 {%0, %1}, %2;" : "=f"(lo), "=f"(hi) : "l"(v));
}
__device__ __forceinline__ ull fma2(ull a, ull b, ull c) {
    ull d; asm("fma.rn.f32x2 %0, %1, %2, %3;" : "=l"(d) : "l"(a), "l"(b), "l"(c));
    return d;
}

__device__ double       g_ssim_acc = 0.0;
__device__ unsigned int g_blk_cnt  = 0;

// tap t (0..10) -> distinct-weight index (symmetry)
#define TAPIDX(t) ((t) < 6 ? (t) : 10 - (t))

extern "C" __global__ void __launch_bounds__(256, 3)
ssim_fused_kernel(const float* __restrict__ F,
                  const float* __restrict__ S1,
                  const float* __restrict__ S2,
                  float* __restrict__ out) {
    extern __shared__ ull vb[];   // [4 pair][64 col][COL_STRIDE rows]

    const int tid = threadIdx.x;
    const int x0 = blockIdx.x * OUT_TW;
    const int y0 = blockIdx.y * OUT_TH;
    const int plane = blockIdx.z;
    const float* __restrict__ Fp  = F  + (size_t)plane * (IMG_H * IMG_W);
    const float* __restrict__ S1p = S1 + (size_t)plane * (IMG_H * IMG_W);
    const float* __restrict__ S2p = S2 + (size_t)plane * (IMG_H * IMG_W);

    // 6 distinct Gaussian taps (sigma=1.5, normalized), packed {w,w}.
    constexpr float G6[6] = {
        0.00102838f, 0.00759874f, 0.03600077f,
        0.10936055f, 0.21300554f, 0.26601173f
    };
    ull W6[6];
    #pragma unroll
    for (int t = 0; t < 6; ++t) {
        unsigned u = __float_as_uint(G6[t]);
        W6[t] = ((ull)u << 32) | u;
    }

    // ---------------- Phase A: vertical blur, two pair-passes ---------------
    {
        const int col   = tid & 63;        // 0..63 input column
        const int chunk = tid >> 6;        // 0..3 -> v-rows [chunk*8, +8)
        const int xg = x0 - 5 + col;
        const int rbase = y0 + chunk * 8 - 5;
        const bool interior = (blockIdx.x >= 1) & (blockIdx.x <= 8) &
                              (blockIdx.y >= 1) & (blockIdx.y <= 14);
        const bool colok = ((unsigned)xg < (unsigned)IMG_W);
        ull* const dst = vb + (size_t)col * COL_STRIDE + chunk * 8;

        // ---- pass 1: loads f,a -> Q0=(f,a), Q1=(fa,aa) -> planes 0,1 ------
        {
            ull acc[8][2];
            #pragma unroll
            for (int j = 0; j < 8; ++j) { acc[j][0] = 0ull; acc[j][1] = 0ull; }

            if (interior) {
                const float* pf = Fp  + (rbase * IMG_W + xg);
                const float* pa = S1p + (rbase * IMG_W + xg);
                #pragma unroll
                for (int r = 0; r < 18; ++r) {
                    const float f = pf[r * IMG_W];
                    const float a = pa[r * IMG_W];
                    const ull Q0 = pk2(f, a);
                    const ull Q1 = pk2(f * a, a * a);
                    const int jlo = (r - 10) > 0 ? (r - 10) : 0;
                    const int jhi = r < 7 ? r : 7;
                    #pragma unroll
                    for (int j = jlo; j <= jhi; ++j) {
                        const ull w = W6[TAPIDX(r - j)];
                        acc[j][0] = fma2(Q0, w, acc[j][0]);
                        acc[j][1] = fma2(Q1, w, acc[j][1]);
                    }
                }
            } else {
                #pragma unroll
                for (int r = 0; r < 18; ++r) {
                    const int ry = rbase + r;
                    float f = 0.0f, a = 0.0f;
                    if (colok && (unsigned)ry < (unsigned)IMG_H) {
                        const int idx = ry * IMG_W + xg;
                        f = Fp[idx]; a = S1p[idx];
                    }
                    const ull Q0 = pk2(f, a);
                    const ull Q1 = pk2(f * a, a * a);
                    const int jlo = (r - 10) > 0 ? (r - 10) : 0;
                    const int jhi = r < 7 ? r : 7;
                    #pragma unroll
                    for (int j = jlo; j <= jhi; ++j) {
                        const ull w = W6[TAPIDX(r - j)];
                        acc[j][0] = fma2(Q0, w, acc[j][0]);
                        acc[j][1] = fma2(Q1, w, acc[j][1]);
                    }
                }
            }
            #pragma unroll
            for (int j = 0; j < 8; ++j) {
                dst[0 * PAIR_STRIDE + j] = acc[j][0];
                dst[1 * PAIR_STRIDE + j] = acc[j][1];
            }
        }

        // ---- pass 2: loads f,b -> Q2=(ff,b), Q3=(bb,fb) -> planes 2,3 -----
        {
            ull acc[8][2];
            #pragma unroll
            for (int j = 0; j < 8; ++j) { acc[j][0] = 0ull; acc[j][1] = 0ull; }

            if (interior) {
                const float* pf = Fp  + (rbase * IMG_W + xg);
                const float* pb = S2p + (rbase * IMG_W + xg);
                #pragma unroll
                for (int r = 0; r < 18; ++r) {
                    const float f = pf[r * IMG_W];
                    const float b = pb[r * IMG_W];
                    const ull Q2 = pk2(f * f, b);
                    const ull Q3 = pk2(b * b, f * b);
                    const int jlo = (r - 10) > 0 ? (r - 10) : 0;
                    const int jhi = r < 7 ? r : 7;
                    #pragma unroll
                    for (int j = jlo; j <= jhi; ++j) {
                        const ull w = W6[TAPIDX(r - j)];
                        acc[j][0] = fma2(Q2, w, acc[j][0]);
                        acc[j][1] = fma2(Q3, w, acc[j][1]);
                    }
                }
            } else {
                #pragma unroll
                for (int r = 0; r < 18; ++r) {
                    const int ry = rbase + r;
                    float f = 0.0f, b = 0.0f;
                    if (colok && (unsigned)ry < (unsigned)IMG_H) {
                        const int idx = ry * IMG_W + xg;
                        f = Fp[idx]; b = S2p[idx];
                    }
                    const ull Q2 = pk2(f * f, b);
                    const ull Q3 = pk2(b * b, f * b);
                    const int jlo = (r - 10) > 0 ? (r - 10) : 0;
                    const int jhi = r < 7 ? r : 7;
                    #pragma unroll
                    for (int j = jlo; j <= jhi; ++j) {
                        const ull w = W6[TAPIDX(r - j)];
                        acc[j][0] = fma2(Q2, w, acc[j][0]);
                        acc[j][1] = fma2(Q3, w, acc[j][1]);
                    }
                }
            }
            #pragma unroll
            for (int j = 0; j < 8; ++j) {
                dst[2 * PAIR_STRIDE + j] = acc[j][0];
                dst[3 * PAIR_STRIDE + j] = acc[j][1];
            }
        }
    }
    __syncthreads();

    // ---------------- Phase B: horizontal blur, two pair-passes -------------
    float lsum = 0.0f;
    {
        const int row   = tid & 31;        // 0..31 (warp lanes = rows)
        const int group = tid >> 5;        // 0..7
        const int c0 = group * 7;          // out-col base (0..49)
        const size_t boff = (size_t)c0 * COL_STRIDE + row;

        ull h0[7], h1[7], h2[7], h3[7];
        #pragma unroll
        for (int j = 0; j < 7; ++j) { h0[j] = 0; h1[j] = 0; h2[j] = 0; h3[j] = 0; }

        // pass over planes 0,1 (lanes read consecutive ull -> conflict-free)
        {
            const ull* __restrict__ s0 = vb + 0 * PAIR_STRIDE + boff;
            const ull* __restrict__ s1 = vb + 1 * PAIR_STRIDE + boff;
            #pragma unroll
            for (int k = 0; k < 17; ++k) {
                const ull w0 = s0[k * COL_STRIDE];
                const ull w1 = s1[k * COL_STRIDE];
                const int jlo = (k - 10) > 0 ? (k - 10) : 0;
                const int jhi = k < 6 ? k : 6;
                #pragma unroll
                for (int j = jlo; j <= jhi; ++j) {
                    const ull w = W6[TAPIDX(k - j)];
                    h0[j] = fma2(w0, w, h0[j]);
                    h1[j] = fma2(w1, w, h1[j]);
                }
            }
        }
        // pass over planes 2,3
        {
            const ull* __restrict__ s2 = vb + 2 * PAIR_STRIDE + boff;
            const ull* __restrict__ s3 = vb + 3 * PAIR_STRIDE + boff;
            #pragma unroll
            for (int k = 0; k < 17; ++k) {
                const ull w2 = s2[k * COL_STRIDE];
                const ull w3 = s3[k * COL_STRIDE];
                const int jlo = (k - 10) > 0 ? (k - 10) : 0;
                const int jhi = k < 6 ? k : 6;
                #pragma unroll
                for (int j = jlo; j <= jhi; ++j) {
                    const ull w = W6[TAPIDX(k - j)];
                    h2[j] = fma2(w2, w, h2[j]);
                    h3[j] = fma2(w3, w, h3[j]);
                }
            }
        }

        const int limit = (OUT_TW < IMG_W - x0) ? OUT_TW : (IMG_W - x0);
        const float C1c = 1e-4f;   // 0.01^2
        const float C2c = 9e-4f;   // 0.03^2
        #pragma unroll
        for (int j = 0; j < 7; ++j) {
            if (c0 + j < limit) {
                float mu1, mu2, Bfa, Baa, Bff, mu3, Bbb, Bfb;
                upk2(mu1, mu2, h0[j]);
                upk2(Bfa, Baa, h1[j]);
                upk2(Bff, mu3, h2[j]);
                upk2(Bbb, Bfb, h3[j]);
                const float m11 = mu1 * mu1, m22 = mu2 * mu2, m33 = mu3 * mu3;
                const float m12 = mu1 * mu2, m13 = mu1 * mu3;
                const float s11 = Bff - m11;
                const float s22 = Baa - m22;
                const float s33 = Bbb - m33;
                const float s12 = Bfa - m12;
                const float s13 = Bfb - m13;
                const float n1 = (2.0f * m12 + C1c) * (2.0f * s12 + C2c);
                const float d1 = (m11 + m22 + C1c) * (s11 + s22 + C2c);
                const float n2 = (2.0f * m13 + C1c) * (2.0f * s13 + C2c);
                const float d2 = (m11 + m33 + C1c) * (s11 + s33 + C2c);
                lsum += __fdividef(n1, d1) + __fdividef(n2, d2);
            }
        }
    }

    // ---------------- reduction + self-finalizing last block ----------------
    #pragma unroll
    for (int o = 16; o; o >>= 1)
        lsum += __shfl_down_sync(0xffffffffu, lsum, o);
    __shared__ float wsum[8];
    if ((tid & 31) == 0) wsum[tid >> 5] = lsum;
    __syncthreads();
    if (tid < 8) {
        float v = wsum[tid];
        #pragma unroll
        for (int o = 4; o; o >>= 1)
            v += __shfl_down_sync(0x000000ffu, v, o);
        if (tid == 0) {
            atomicAdd(&g_ssim_acc, (double)v);
            __threadfence();
            const unsigned old = atomicAdd(&g_blk_cnt, 1u);
            if (old == (unsigned)(N_BLOCKS - 1)) {
                __threadfence();
                volatile double* va = &g_ssim_acc;
                const double total = *va;
                const double npix = (double)N_PLANES * IMG_H * IMG_W;
                out[0] = (float)(1.0 - total / (2.0 * npix));
                *va = 0.0;                       // reset for next replay
                *(volatile unsigned*)&g_blk_cnt = 0u;
                __threadfence();
            }
        }
    }
}

extern "C" void kernel_launch(void* const* d_in, const int* in_sizes, int n_in,
                              void* d_out, int out_size) {
    (void)in_sizes; (void)n_in; (void)out_size;
    const float* F  = (const float*)d_in[0];
    const float* S1 = (const float*)d_in[1];
    const float* S2 = (const float*)d_in[2];
    float* out = (float*)d_out;

    cudaFuncSetAttribute(ssim_fused_kernel,
                         cudaFuncAttributeMaxDynamicSharedMemorySize,
                         SMEM_BYTES);

    dim3 grid(GRID_X, GRID_Y, N_PLANES);   // 10 x 16 x 48 = 7680 blocks
    ssim_fused_kernel<<<grid, 256, SMEM_BYTES>>>(F, S1, S2, out);
}

// round 16
// speedup vs baseline: 1.1327x; 1.0343x over previous
#include <cuda_runtime.h>
#include <cuda_bf16.h>

// ---------------------------------------------------------------------------
// Fused SSIM loss, separable 11-tap Gaussian, f32x2-packed (FFMA2) math.
//   result = 1 - (mean(ssim(f,s1)) + mean(ssim(f,s2))) / 2
// Phase A is split into two pair-passes, each with EXPLICIT load batching:
// all 36 LDGs issue back-to-back (max MLP, one scoreboard wait) before any
// fma consumes them.
//   pass 1: loads f,a -> planes Q0=(f,a), Q1=(f*a,a^2)
//   pass 2: loads f,b -> planes Q2=(f^2,b), Q3=(b^2,f*b)
// v-buffer TRANSPOSED [pair][col][row] -> conflict-free LDS.64 in phase B.
// ---------------------------------------------------------------------------

#define IMG_W 512
#define IMG_H 512
#define N_PLANES 48               // B*C = 16*3
#define OUT_TW 54
#define OUT_TH 32
#define IN_TW 64
#define COL_STRIDE 33             // ull per column (32 rows + 1 pad)
#define PAIR_STRIDE (IN_TW * COL_STRIDE)
#define SMEM_ULL (4 * PAIR_STRIDE + 128)          // +128 overread slack
#define SMEM_BYTES (SMEM_ULL * 8)                 // 68608
#define GRID_X 10
#define GRID_Y 16
#define N_BLOCKS (GRID_X * GRID_Y * N_PLANES)     // 7680

typedef unsigned long long ull;

__device__ __forceinline__ ull pk2(float lo, float hi) {
    ull r; asm("mov.b64 %0, {%1, %2};" : "=l"(r) : "f"(lo), "f"(hi)); return r;
}
__device__ __forceinline__ void upk2(float& lo, float& hi, ull v) {
    asm("mov.b64 {%0, %1}, %2;" : "=f"(lo), "=f"(hi) : "l"(v));
}
__device__ __forceinline__ ull fma2(ull a, ull b, ull c) {
    ull d; asm("fma.rn.f32x2 %0, %1, %2, %3;" : "=l"(d) : "l"(a), "l"(b), "l"(c));
    return d;
}

__device__ double       g_ssim_acc = 0.0;
__device__ unsigned int g_blk_cnt  = 0;

// tap t (0..10) -> distinct-weight index (symmetry)
#define TAPIDX(t) ((t) < 6 ? (t) : 10 - (t))

extern "C" __global__ void __launch_bounds__(256, 2)
ssim_fused_kernel(const float* __restrict__ F,
                  const float* __restrict__ S1,
                  const float* __restrict__ S2,
                  float* __restrict__ out) {
    extern __shared__ ull vb[];   // [4 pair][64 col][COL_STRIDE rows]

    const int tid = threadIdx.x;
    const int x0 = blockIdx.x * OUT_TW;
    const int y0 = blockIdx.y * OUT_TH;
    const int plane = blockIdx.z;
    const float* __restrict__ Fp  = F  + (size_t)plane * (IMG_H * IMG_W);
    const float* __restrict__ S1p = S1 + (size_t)plane * (IMG_H * IMG_W);
    const float* __restrict__ S2p = S2 + (size_t)plane * (IMG_H * IMG_W);

    // 6 distinct Gaussian taps (sigma=1.5, normalized), packed {w,w}.
    constexpr float G6[6] = {
        0.00102838f, 0.00759874f, 0.03600077f,
        0.10936055f, 0.21300554f, 0.26601173f
    };
    ull W6[6];
    #pragma unroll
    for (int t = 0; t < 6; ++t) {
        unsigned u = __float_as_uint(G6[t]);
        W6[t] = ((ull)u << 32) | u;
    }

    // ---------------- Phase A: vertical blur, two batched pair-passes -------
    {
        const int col   = tid & 63;        // 0..63 input column
        const int chunk = tid >> 6;        // 0..3 -> v-rows [chunk*8, +8)
        const int xg = x0 - 5 + col;
        const int rbase = y0 + chunk * 8 - 5;
        const bool interior = (blockIdx.x >= 1) & (blockIdx.x <= 8) &
                              (blockIdx.y >= 1) & (blockIdx.y <= 14);
        const bool colok = ((unsigned)xg < (unsigned)IMG_W);
        ull* const dst = vb + (size_t)col * COL_STRIDE + chunk * 8;

        // ---- pass 1: f,a -> Q0=(f,a), Q1=(fa,aa) -> planes 0,1 -------------
        {
            float fv[18], sv[18];
            if (interior) {
                const float* pf = Fp  + (rbase * IMG_W + xg);
                const float* pa = S1p + (rbase * IMG_W + xg);
                #pragma unroll
                for (int r = 0; r < 18; ++r) fv[r] = pf[r * IMG_W];
                #pragma unroll
                for (int r = 0; r < 18; ++r) sv[r] = pa[r * IMG_W];
            } else {
                #pragma unroll
                for (int r = 0; r < 18; ++r) {
                    const int ry = rbase + r;
                    fv[r] = 0.0f; sv[r] = 0.0f;
                    if (colok && (unsigned)ry < (unsigned)IMG_H) {
                        const int idx = ry * IMG_W + xg;
                        fv[r] = Fp[idx]; sv[r] = S1p[idx];
                    }
                }
            }

            ull acc[8][2];
            #pragma unroll
            for (int j = 0; j < 8; ++j) { acc[j][0] = 0ull; acc[j][1] = 0ull; }

            #pragma unroll
            for (int r = 0; r < 18; ++r) {
                const ull Q0 = pk2(fv[r], sv[r]);
                const ull Q1 = pk2(fv[r] * sv[r], sv[r] * sv[r]);
                const int jlo = (r - 10) > 0 ? (r - 10) : 0;
                const int jhi = r < 7 ? r : 7;
                #pragma unroll
                for (int j = jlo; j <= jhi; ++j) {
                    const ull w = W6[TAPIDX(r - j)];
                    acc[j][0] = fma2(Q0, w, acc[j][0]);
                    acc[j][1] = fma2(Q1, w, acc[j][1]);
                }
            }
            #pragma unroll
            for (int j = 0; j < 8; ++j) {
                dst[0 * PAIR_STRIDE + j] = acc[j][0];
                dst[1 * PAIR_STRIDE + j] = acc[j][1];
            }
        }

        // ---- pass 2: f,b -> Q2=(ff,b), Q3=(bb,fb) -> planes 2,3 ------------
        {
            float fv[18], sv[18];
            if (interior) {
                const float* pf = Fp  + (rbase * IMG_W + xg);
                const float* pb = S2p + (rbase * IMG_W + xg);
                #pragma unroll
                for (int r = 0; r < 18; ++r) fv[r] = pf[r * IMG_W];
                #pragma unroll
                for (int r = 0; r < 18; ++r) sv[r] = pb[r * IMG_W];
            } else {
                #pragma unroll
                for (int r = 0; r < 18; ++r) {
                    const int ry = rbase + r;
                    fv[r] = 0.0f; sv[r] = 0.0f;
                    if (colok && (unsigned)ry < (unsigned)IMG_H) {
                        const int idx = ry * IMG_W + xg;
                        fv[r] = Fp[idx]; sv[r] = S2p[idx];
                    }
                }
            }

            ull acc[8][2];
            #pragma unroll
            for (int j = 0; j < 8; ++j) { acc[j][0] = 0ull; acc[j][1] = 0ull; }

            #pragma unroll
            for (int r = 0; r < 18; ++r) {
                const ull Q2 = pk2(fv[r] * fv[r], sv[r]);
                const ull Q3 = pk2(sv[r] * sv[r], fv[r] * sv[r]);
                const int jlo = (r - 10) > 0 ? (r - 10) : 0;
                const int jhi = r < 7 ? r : 7;
                #pragma unroll
                for (int j = jlo; j <= jhi; ++j) {
                    const ull w = W6[TAPIDX(r - j)];
                    acc[j][0] = fma2(Q2, w, acc[j][0]);
                    acc[j][1] = fma2(Q3, w, acc[j][1]);
                }
            }
            #pragma unroll
            for (int j = 0; j < 8; ++j) {
                dst[2 * PAIR_STRIDE + j] = acc[j][0];
                dst[3 * PAIR_STRIDE + j] = acc[j][1];
            }
        }
    }
    __syncthreads();

    // ---------------- Phase B: horizontal blur + epilogue -------------------
    float lsum = 0.0f;
    {
        const int row   = tid & 31;        // 0..31 (warp lanes = rows)
        const int group = tid >> 5;        // 0..7
        const int c0 = group * 7;          // out-col base (0..49)
        const size_t boff = (size_t)c0 * COL_STRIDE + row;

        ull hb[4][7];
        #pragma unroll
        for (int p = 0; p < 4; ++p) {
            const ull* __restrict__ src = vb + (size_t)p * PAIR_STRIDE + boff;
            #pragma unroll
            for (int j = 0; j < 7; ++j) hb[p][j] = 0ull;
            #pragma unroll
            for (int k = 0; k < 17; ++k) {
                const ull w = src[k * COL_STRIDE];
                const int jlo = (k - 10) > 0 ? (k - 10) : 0;
                const int jhi = k < 6 ? k : 6;
                #pragma unroll
                for (int j = jlo; j <= jhi; ++j)
                    hb[p][j] = fma2(w, W6[TAPIDX(k - j)], hb[p][j]);
            }
        }

        const int limit = (OUT_TW < IMG_W - x0) ? OUT_TW : (IMG_W - x0);
        const float C1c = 1e-4f;   // 0.01^2
        const float C2c = 9e-4f;   // 0.03^2
        #pragma unroll
        for (int j = 0; j < 7; ++j) {
            if (c0 + j < limit) {
                float mu1, mu2, Bfa, Baa, Bff, mu3, Bbb, Bfb;
                upk2(mu1, mu2, hb[0][j]);
                upk2(Bfa, Baa, hb[1][j]);
                upk2(Bff, mu3, hb[2][j]);
                upk2(Bbb, Bfb, hb[3][j]);
                const float m11 = mu1 * mu1, m22 = mu2 * mu2, m33 = mu3 * mu3;
                const float m12 = mu1 * mu2, m13 = mu1 * mu3;
                const float s11 = Bff - m11;
                const float s22 = Baa - m22;
                const float s33 = Bbb - m33;
                const float s12 = Bfa - m12;
                const float s13 = Bfb - m13;
                const float n1 = (2.0f * m12 + C1c) * (2.0f * s12 + C2c);
                const float d1 = (m11 + m22 + C1c) * (s11 + s22 + C2c);
                const float n2 = (2.0f * m13 + C1c) * (2.0f * s13 + C2c);
                const float d2 = (m11 + m33 + C1c) * (s11 + s33 + C2c);
                lsum += __fdividef(n1, d1) + __fdividef(n2, d2);
            }
        }
    }

    // ---------------- reduction + self-finalizing last block ----------------
    #pragma unroll
    for (int o = 16; o; o >>= 1)
        lsum += __shfl_down_sync(0xffffffffu, lsum, o);
    __shared__ float wsum[8];
    if ((tid & 31) == 0) wsum[tid >> 5] = lsum;
    __syncthreads();
    if (tid < 8) {
        float v = wsum[tid];
        #pragma unroll
        for (int o = 4; o; o >>= 1)
            v += __shfl_down_sync(0x000000ffu, v, o);
        if (tid == 0) {
            atomicAdd(&g_ssim_acc, (double)v);
            __threadfence();
            const unsigned old = atomicAdd(&g_blk_cnt, 1u);
            if (old == (unsigned)(N_BLOCKS - 1)) {
                __threadfence();
                volatile double* va = &g_ssim_acc;
                const double total = *va;
                const double npix = (double)N_PLANES * IMG_H * IMG_W;
                out[0] = (float)(1.0 - total / (2.0 * npix));
                *va = 0.0;                       // reset for next replay
                *(volatile unsigned*)&g_blk_cnt = 0u;
                __threadfence();
            }
        }
    }
}

extern "C" void kernel_launch(void* const* d_in, const int* in_sizes, int n_in,
                              void* d_out, int out_size) {
    (void)in_sizes; (void)n_in; (void)out_size;
    const float* F  = (const float*)d_in[0];
    const float* S1 = (const float*)d_in[1];
    const float* S2 = (const float*)d_in[2];
    float* out = (float*)d_out;

    cudaFuncSetAttribute(ssim_fused_kernel,
                         cudaFuncAttributeMaxDynamicSharedMemorySize,
                         SMEM_BYTES);

    dim3 grid(GRID_X, GRID_Y, N_PLANES);   // 10 x 16 x 48 = 7680 blocks
    ssim_fused_kernel<<<grid, 256, SMEM_BYTES>>>(F, S1, S2, out);
}